// round 3
// baseline (speedup 1.0000x reference)
#include <cuda_runtime.h>
#include <cuda_bf16.h>

// Downsampler: depthwise 4x4 conv, stride 4, VALID -> non-overlapping weighted
// 4x4 block reduction. Pure streaming: 512MB read, 8MB write, DRAM-bound.
// R3: 4 horizontal outputs per thread -> 16 front-batched LDG.128 (MLP_p1=16),
// __ldcs streaming loads, single float4 __stcs store.

#define IW 1024
#define OW 256
#define OH 256
#define OPT 4

__global__ __launch_bounds__(256, 2) void downsample_kernel(
    const float* __restrict__ x,
    const float* __restrict__ kw,
    float* __restrict__ out)
{
    int idx = blockIdx.x * blockDim.x + threadIdx.x;   // quad index
    int oxq = idx & (OW / OPT - 1);          // 0..63
    int oy  = (idx >> 6) & (OH - 1);
    int nc  = idx >> 14;

    float k00 = __ldg(kw + 0),  k01 = __ldg(kw + 1),  k02 = __ldg(kw + 2),  k03 = __ldg(kw + 3);
    float k10 = __ldg(kw + 4),  k11 = __ldg(kw + 5),  k12 = __ldg(kw + 6),  k13 = __ldg(kw + 7);
    float k20 = __ldg(kw + 8),  k21 = __ldg(kw + 9),  k22 = __ldg(kw + 10), k23 = __ldg(kw + 11);
    float k30 = __ldg(kw + 12), k31 = __ldg(kw + 13), k32 = __ldg(kw + 14), k33 = __ldg(kw + 15);

    const float4* base = reinterpret_cast<const float4*>(
        x + ((size_t)nc * IW + (size_t)oy * 4) * IW) + (size_t)oxq * 4;

    // 16 streaming 128-bit loads, all issued up front (MLP=16)
    float4 a0 = __ldcs(base + 0 * (IW/4) + 0);
    float4 b0 = __ldcs(base + 0 * (IW/4) + 1);
    float4 c0 = __ldcs(base + 0 * (IW/4) + 2);
    float4 d0 = __ldcs(base + 0 * (IW/4) + 3);
    float4 a1 = __ldcs(base + 1 * (IW/4) + 0);
    float4 b1 = __ldcs(base + 1 * (IW/4) + 1);
    float4 c1 = __ldcs(base + 1 * (IW/4) + 2);
    float4 d1 = __ldcs(base + 1 * (IW/4) + 3);
    float4 a2 = __ldcs(base + 2 * (IW/4) + 0);
    float4 b2 = __ldcs(base + 2 * (IW/4) + 1);
    float4 c2 = __ldcs(base + 2 * (IW/4) + 2);
    float4 d2 = __ldcs(base + 2 * (IW/4) + 3);
    float4 a3 = __ldcs(base + 3 * (IW/4) + 0);
    float4 b3 = __ldcs(base + 3 * (IW/4) + 1);
    float4 c3 = __ldcs(base + 3 * (IW/4) + 2);
    float4 d3 = __ldcs(base + 3 * (IW/4) + 3);

    float4 r;
    r.x  = a0.x * k00 + a0.y * k01 + a0.z * k02 + a0.w * k03;
    r.x += a1.x * k10 + a1.y * k11 + a1.z * k12 + a1.w * k13;
    r.x += a2.x * k20 + a2.y * k21 + a2.z * k22 + a2.w * k23;
    r.x += a3.x * k30 + a3.y * k31 + a3.z * k32 + a3.w * k33;

    r.y  = b0.x * k00 + b0.y * k01 + b0.z * k02 + b0.w * k03;
    r.y += b1.x * k10 + b1.y * k11 + b1.z * k12 + b1.w * k13;
    r.y += b2.x * k20 + b2.y * k21 + b2.z * k22 + b2.w * k23;
    r.y += b3.x * k30 + b3.y * k31 + b3.z * k32 + b3.w * k33;

    r.z  = c0.x * k00 + c0.y * k01 + c0.z * k02 + c0.w * k03;
    r.z += c1.x * k10 + c1.y * k11 + c1.z * k12 + c1.w * k13;
    r.z += c2.x * k20 + c2.y * k21 + c2.z * k22 + c2.w * k23;
    r.z += c3.x * k30 + c3.y * k31 + c3.z * k32 + c3.w * k33;

    r.w  = d0.x * k00 + d0.y * k01 + d0.z * k02 + d0.w * k03;
    r.w += d1.x * k10 + d1.y * k11 + d1.z * k12 + d1.w * k13;
    r.w += d2.x * k20 + d2.y * k21 + d2.z * k22 + d2.w * k23;
    r.w += d3.x * k30 + d3.y * k31 + d3.z * k32 + d3.w * k33;

    __stcs(reinterpret_cast<float4*>(out) + idx, r);
}

extern "C" void kernel_launch(void* const* d_in, const int* in_sizes, int n_in,
                              void* d_out, int out_size)
{
    const float* x  = (const float*)d_in[0];
    const float* kw = (const float*)d_in[1];
    float* out = (float*)d_out;

    int total = out_size / OPT;     // thread count (quads)
    int threads = 256;
    int blocks = (total + threads - 1) / threads;
    downsample_kernel<<<blocks, threads>>>(x, kw, out);
}